// round 3
// baseline (speedup 1.0000x reference)
#include <cuda_runtime.h>
#include <math.h>

// ---------------- problem constants (shape-specialized) ----------------
#define NB      2            // batch
#define MB      512          // boxes
#define CIN     512          // feature channels
#define POOLSZ  14
#define PP      196          // 14*14
#define HID     1024
#define NCLS    81
#define KFC     (CIN*PP)     // 100352
#define OC      256          // conv out channels
#define O1      (MB*NCLS)    // 41472 per-output stride in d_out

// ---------------- packed fp32x2 helpers (sm_103a FFMA2 path) ----------------
__device__ __forceinline__ unsigned long long pk2(float x, float y) {
    unsigned long long r;
    asm("mov.b64 %0, {%1, %2};" : "=l"(r) : "f"(x), "f"(y));
    return r;
}
__device__ __forceinline__ void fma2(unsigned long long& d, unsigned long long a,
                                     unsigned long long b) {
    asm("fma.rn.f32x2 %0, %1, %2, %3;" : "=l"(d) : "l"(a), "l"(b), "l"(d));
}
__device__ __forceinline__ float2 upk(unsigned long long v) {
    float2 f;
    asm("mov.b64 {%0, %1}, %2;" : "=f"(f.x), "=f"(f.y) : "l"(v));
    return f;
}

// ---------------- scratch (device globals; no runtime alloc) ----------------
__device__ float g_pooled[(size_t)MB*CIN*PP];   // ~205 MB
__device__ float g_h[MB*HID];
__device__ float g_csum[MB*OC];
__device__ float g_wT[CIN*9*OC];                // conv weights [cin*9][oc]
__device__ int   g_lvl[MB];
__device__ float g_boxp[MB*4];

// ---------------- setup: FPN level + scaled box params ----------------
__global__ void setup_boxes(const float* __restrict__ boxes,
                            const int* __restrict__ ih, const int* __restrict__ iw) {
    int m = blockIdx.x * blockDim.x + threadIdx.x;
    if (m >= MB) return;
    float x1 = boxes[m*4+0], y1 = boxes[m*4+1];
    float x2 = boxes[m*4+2], y2 = boxes[m*4+3];
    float alpha = (224.0f/800.0f) * fminf((float)(*ih), (float)(*iw));
    float bw = fabsf(x2-x1), bh = fabsf(y2-y1);
    float s = sqrtf(fmaxf(bw*bh, 1e-6f));
    float k = floorf(4.0f + log2f(s/alpha));
    float kl = fminf(fmaxf(k - 2.0f, 0.0f), 3.0f);
    int lvl = (int)kl;
    g_lvl[m] = lvl;
    float scale = 1.0f / (float)(4 << lvl);
    // match reference fp32 ordering: scale each coord first, then subtract
    float x1s = x1*scale, y1s = y1*scale, x2s = x2*scale, y2s = y2*scale;
    g_boxp[m*4+0] = x1s;
    g_boxp[m*4+1] = y1s;
    g_boxp[m*4+2] = x2s - x1s;
    g_boxp[m*4+3] = y2s - y1s;
}

// ---------------- conv weight transpose: [oc][cin*9] -> [cin*9][oc] ----------------
__global__ void wconv_transpose(const float* __restrict__ w) {
    int i = blockIdx.x * 256 + threadIdx.x;
    if (i >= OC*CIN*9) return;
    int oc = i / (CIN*9);
    int r  = i % (CIN*9);
    g_wT[r*OC + oc] = w[i];
}

// ---------------- RoIAlign: block=(box m, channel c), 196 bin threads ----------------
__global__ void roi_kernel(const float* __restrict__ p2, const float* __restrict__ p3,
                           const float* __restrict__ p4, const float* __restrict__ p5,
                           const int* __restrict__ bidx) {
    int m = blockIdx.x;
    int c = blockIdx.y;
    int t = threadIdx.x;
    if (t >= PP) return;
    int lvl = g_lvl[m];
    const float* f; int H, W;
    if      (lvl == 0) { f = p2; H = 200; W = 200; }
    else if (lvl == 1) { f = p3; H = 100; W = 100; }
    else if (lvl == 2) { f = p4; H = 50;  W = 50;  }
    else               { f = p5; H = 25;  W = 25;  }
    int b = bidx[m];
    float x1 = g_boxp[m*4+0], y1 = g_boxp[m*4+1];
    float dx = g_boxp[m*4+2], dy = g_boxp[m*4+3];
    int py = t / POOLSZ, px = t % POOLSZ;
    float gx = x1 + ((float)px + 0.5f) * (1.0f/POOLSZ) * dx;
    float gy = y1 + ((float)py + 0.5f) * (1.0f/POOLSZ) * dy;
    float x0f = floorf(gx), y0f = floorf(gy);
    float lx = gx - x0f, ly = gy - y0f;
    int xi0 = min(max((int)x0f,     0), W-1);
    int xi1 = min(max((int)x0f + 1, 0), W-1);
    int yi0 = min(max((int)y0f,     0), H-1);
    int yi1 = min(max((int)y0f + 1, 0), H-1);
    const float* base = f + ((size_t)(b*CIN + c)) * H * W;
    float v00 = base[yi0*W + xi0];
    float v01 = base[yi0*W + xi1];
    float v10 = base[yi1*W + xi0];
    float v11 = base[yi1*W + xi1];
    float val = v00*(1.f-ly)*(1.f-lx) + v01*(1.f-ly)*lx
              + v10*ly*(1.f-lx)       + v11*ly*lx;
    g_pooled[((size_t)m*CIN + c)*PP + t] = val;
}

// ---------------- FC1 GEMM: [512 x 100352] @ [100352 x 1024] + bias, ReLU ------------
// 64x64 tile, 256 threads, 4x4 per thread; f32x2 packed FMAs.
// B smem tile stored DUPLICATED so b-pairs {b,b} load directly (no packs).
#define BM 64
#define BN 64
#define BK 16
__global__ __launch_bounds__(256)
void gemm1_kernel(const float* __restrict__ B, const float* __restrict__ bias) {
    __shared__ __align__(16) float As[BK][BM+4];    // [k][m]
    __shared__ __align__(16) float Bsd[BK][2*BN];   // [k][2n], value duplicated
    int t  = threadIdx.x;
    int mBase = blockIdx.y * BM;
    int nBase = blockIdx.x * BN;
    int ty = t / 16, tx = t % 16;
    int arow = t / 4,  acol = (t % 4) * 4;    // A tile 64x16
    int brow = t / 16, bcol = (t % 16) * 4;   // B tile 16x64
    const float* Ap = g_pooled + (size_t)(mBase + arow) * KFC + acol;
    const float* Bp = B + (size_t)brow * HID + nBase + bcol;
    unsigned long long acc2[2][4];   // [m-pair][n]; lo = row ty*4+2*ip, hi = +1
    #pragma unroll
    for (int ip = 0; ip < 2; ip++)
        #pragma unroll
        for (int j = 0; j < 4; j++) acc2[ip][j] = 0ull;

    for (int k0 = 0; k0 < KFC; k0 += BK) {
        float4 a  = *(const float4*)(Ap + k0);
        float4 bv = *(const float4*)(Bp + (size_t)k0 * HID);
        __syncthreads();
        As[acol+0][arow] = a.x; As[acol+1][arow] = a.y;
        As[acol+2][arow] = a.z; As[acol+3][arow] = a.w;
        {
            unsigned long long* bd = (unsigned long long*)&Bsd[brow][2*bcol];
            bd[0] = pk2(bv.x, bv.x);
            bd[1] = pk2(bv.y, bv.y);
            bd[2] = pk2(bv.z, bv.z);
            bd[3] = pk2(bv.w, bv.w);
        }
        __syncthreads();
        #pragma unroll
        for (int kk = 0; kk < BK; kk++) {
            ulonglong2 ap = *(const ulonglong2*)&As[kk][ty*4];      // {a0,a1},{a2,a3}
            ulonglong2 b01 = *(const ulonglong2*)&Bsd[kk][8*tx];    // {b0,b0},{b1,b1}
            ulonglong2 b23 = *(const ulonglong2*)&Bsd[kk][8*tx+4];  // {b2,b2},{b3,b3}
            fma2(acc2[0][0], ap.x, b01.x);
            fma2(acc2[0][1], ap.x, b01.y);
            fma2(acc2[0][2], ap.x, b23.x);
            fma2(acc2[0][3], ap.x, b23.y);
            fma2(acc2[1][0], ap.y, b01.x);
            fma2(acc2[1][1], ap.y, b01.y);
            fma2(acc2[1][2], ap.y, b23.x);
            fma2(acc2[1][3], ap.y, b23.y);
        }
    }
    #pragma unroll
    for (int ip = 0; ip < 2; ip++) {
        #pragma unroll
        for (int j = 0; j < 4; j++) {
            float2 v = upk(acc2[ip][j]);
            int n = nBase + tx*4 + j;
            float bb = bias[n];
            int m0 = mBase + ty*4 + 2*ip;
            g_h[(m0+0)*HID + n] = fmaxf(v.x + bb, 0.0f);
            g_h[(m0+1)*HID + n] = fmaxf(v.y + bb, 0.0f);
        }
    }
}

// ---------------- conv 3x3 SAME (512->256) + bias + ReLU + spatial sum ----------------
// block = (box m, oc-block of 64). threads = 224: tid = pg*8 + ocg
//   pg in [0,28): 7 consecutive pixels of one row (row = pg>>1, x0 = (pg&1)*7)
//   ocg in [0,8): oc = ocBase + ocg*8 .. +7   (handled as 4 packed oc-pairs)
__global__ __launch_bounds__(224)
void conv_kernel(const float* __restrict__ bconv) {
    __shared__ __align__(16) float sIn[8*16*16];   // 8 cin x padded 16x16
    __shared__ __align__(16) float sW[8*9*64];     // [cin][k][oc64]
    int m = blockIdx.x;
    int ocBase = blockIdx.y * 64;
    int t = threadIdx.x;
    int pg  = t >> 3;
    int ocg = t & 7;
    int py  = pg >> 1;
    int x0  = (pg & 1) * 7;
    unsigned long long acc2[4][7];   // [oc-pair][pixel]; lo = oc 2jp, hi = 2jp+1
    #pragma unroll
    for (int jp = 0; jp < 4; jp++)
        #pragma unroll
        for (int i = 0; i < 7; i++) acc2[jp][i] = 0ull;

    for (int cb = 0; cb < 64; cb++) {           // 64 chunks of 8 cin
        __syncthreads();
        // load padded input chunk
        for (int i = t; i < 8*256; i += 224) {
            int cin = i >> 8;
            int r   = (i >> 4) & 15;
            int c   = i & 15;
            int ry = r - 1, cx = c - 1;
            float v = 0.0f;
            if (ry >= 0 && ry < POOLSZ && cx >= 0 && cx < POOLSZ)
                v = g_pooled[((size_t)m*CIN + (cb*8 + cin))*PP + ry*POOLSZ + cx];
            sIn[i] = v;
        }
        // load weight chunk: sW[(cin*9+k)*64 + oc]
        for (int i = t; i < 8*9*64; i += 224) {
            int cin = i / 576;
            int r   = i % 576;        // k*64 + oc
            int k   = r >> 6;
            int oc  = r & 63;
            sW[i] = g_wT[((cb*8 + cin)*9 + k)*OC + ocBase + oc];
        }
        __syncthreads();
        for (int cin = 0; cin < 8; cin++) {
            #pragma unroll
            for (int ky = 0; ky < 3; ky++) {
                // pack this input row once, reused across kx
                unsigned long long row[9];
                #pragma unroll
                for (int c = 0; c < 9; c++) {
                    float v = sIn[cin*256 + (py + ky)*16 + (x0 + c)];
                    row[c] = pk2(v, v);
                }
                #pragma unroll
                for (int kx = 0; kx < 3; kx++) {
                    const ulonglong2* wp =
                        (const ulonglong2*)&sW[(cin*9 + ky*3 + kx)*64 + ocg*8];
                    ulonglong2 wa = wp[0];   // {w0,w1},{w2,w3}
                    ulonglong2 wb = wp[1];   // {w4,w5},{w6,w7}
                    #pragma unroll
                    for (int i = 0; i < 7; i++) {
                        fma2(acc2[0][i], wa.x, row[i + kx]);
                        fma2(acc2[1][i], wa.y, row[i + kx]);
                        fma2(acc2[2][i], wb.x, row[i + kx]);
                        fma2(acc2[3][i], wb.y, row[i + kx]);
                    }
                }
            }
        }
    }
    // bias + relu + per-thread partial spatial sum, then smem reduce over pg
    __syncthreads();
    float* sRed = sIn;    // reuse: 28*64 = 1792 <= 2048
    #pragma unroll
    for (int jp = 0; jp < 4; jp++) {
        float bv0 = bconv[ocBase + ocg*8 + 2*jp + 0];
        float bv1 = bconv[ocBase + ocg*8 + 2*jp + 1];
        float s0 = 0.0f, s1 = 0.0f;
        #pragma unroll
        for (int i = 0; i < 7; i++) {
            float2 v = upk(acc2[jp][i]);
            s0 += fmaxf(v.x + bv0, 0.0f);
            s1 += fmaxf(v.y + bv1, 0.0f);
        }
        sRed[pg*64 + ocg*8 + 2*jp + 0] = s0;
        sRed[pg*64 + ocg*8 + 2*jp + 1] = s1;
    }
    __syncthreads();
    if (t < 64) {
        float tot = 0.0f;
        #pragma unroll
        for (int pgi = 0; pgi < 28; pgi++) tot += sRed[pgi*64 + t];
        g_csum[m*OC + ocBase + t] = tot;
    }
}

// ---------------- cls / box heads + softmax ----------------
__global__ void cls_kernel(const float* __restrict__ wcls, const float* __restrict__ bcls,
                           const float* __restrict__ wbox, const float* __restrict__ bbox,
                           float* __restrict__ out) {
    int m = blockIdx.x;
    int t = threadIdx.x;
    __shared__ float sh[HID];
    __shared__ float lg[NCLS];
    __shared__ float red[2];
    for (int i = t; i < HID; i += 128) sh[i] = g_h[m*HID + i];
    __syncthreads();
    if (t < NCLS) {
        float a = bcls[t], r = bbox[t];
        for (int k = 0; k < HID; k++) {
            float hv = sh[k];
            a += hv * wcls[k*NCLS + t];
            r += hv * wbox[k*NCLS + t];
        }
        lg[t] = a;
        out[O1 + m*NCLS + t] = r;
    }
    __syncthreads();
    if (t == 0) {
        float mx = lg[0];
        for (int i = 1; i < NCLS; i++) mx = fmaxf(mx, lg[i]);
        red[0] = mx;
    }
    __syncthreads();
    if (t < NCLS) lg[t] = expf(lg[t] - red[0]);
    __syncthreads();
    if (t == 0) {
        float s = 0.0f;
        for (int i = 0; i < NCLS; i++) s += lg[i];
        red[1] = s;
    }
    __syncthreads();
    if (t < NCLS) out[m*NCLS + t] = lg[t] / red[1];
}

// ---------------- mask head: mean -> FC -> sigmoid ----------------
__global__ void mask_kernel(const float* __restrict__ wmfc, const float* __restrict__ bmfc,
                            float* __restrict__ out) {
    int m = blockIdx.x;
    int t = threadIdx.x;
    __shared__ float sm_[OC];
    for (int i = t; i < OC; i += 96) sm_[i] = g_csum[m*OC + i] * (1.0f/196.0f);
    __syncthreads();
    if (t < NCLS) {
        float a = bmfc[t];
        for (int o = 0; o < OC; o++) a += sm_[o] * wmfc[o*NCLS + t];
        out[2*O1 + m*NCLS + t] = 1.0f / (1.0f + expf(-a));
    }
}

// ---------------- launch ----------------
extern "C" void kernel_launch(void* const* d_in, const int* in_sizes, int n_in,
                              void* d_out, int out_size) {
    const float* p2    = (const float*)d_in[0];
    const float* p3    = (const float*)d_in[1];
    const float* p4    = (const float*)d_in[2];
    const float* p5    = (const float*)d_in[3];
    const float* boxes = (const float*)d_in[4];
    const int*   bidx  = (const int*)  d_in[5];
    const float* wfc1  = (const float*)d_in[6];
    const float* bfc1  = (const float*)d_in[7];
    const float* wcls  = (const float*)d_in[8];
    const float* bcls  = (const float*)d_in[9];
    const float* wbox  = (const float*)d_in[10];
    const float* bbox  = (const float*)d_in[11];
    const float* wconv = (const float*)d_in[12];
    const float* bconv = (const float*)d_in[13];
    const float* wmfc  = (const float*)d_in[14];
    const float* bmfc  = (const float*)d_in[15];
    const int*   ih    = (const int*)  d_in[16];
    const int*   iw    = (const int*)  d_in[17];
    float* out = (float*)d_out;

    setup_boxes<<<1, 512>>>(boxes, ih, iw);
    wconv_transpose<<<(OC*CIN*9 + 255)/256, 256>>>(wconv);
    roi_kernel<<<dim3(MB, CIN), 224>>>(p2, p3, p4, p5, bidx);
    gemm1_kernel<<<dim3(HID/BN, MB/BM), 256>>>(wfc1, bfc1);
    conv_kernel<<<dim3(MB, OC/64), 224>>>(bconv);
    cls_kernel<<<MB, 128>>>(wcls, bcls, wbox, bbox, out);
    mask_kernel<<<MB, 96>>>(wmfc, bmfc, out);
}

// round 4
// speedup vs baseline: 1.3219x; 1.3219x over previous
#include <cuda_runtime.h>
#include <math.h>

// ---------------- problem constants (shape-specialized) ----------------
#define NB      2            // batch
#define MB      512          // boxes
#define CIN     512          // feature channels
#define POOLSZ  14
#define PP      196          // 14*14
#define HID     1024
#define NCLS    81
#define KFC     (CIN*PP)     // 100352
#define OC      256          // conv out channels
#define O1      (MB*NCLS)    // 41472 per-output stride in d_out
#define KS      2            // split-K factor for FC1

// ---------------- packed fp32x2 helpers (sm_103a FFMA2 path) ----------------
__device__ __forceinline__ unsigned long long pk2(float x, float y) {
    unsigned long long r;
    asm("mov.b64 %0, {%1, %2};" : "=l"(r) : "f"(x), "f"(y));
    return r;
}
__device__ __forceinline__ void fma2(unsigned long long& d, unsigned long long a,
                                     unsigned long long b) {
    asm("fma.rn.f32x2 %0, %1, %2, %3;" : "=l"(d) : "l"(a), "l"(b), "l"(d));
}
__device__ __forceinline__ float2 upk(unsigned long long v) {
    float2 f;
    asm("mov.b64 {%0, %1}, %2;" : "=f"(f.x), "=f"(f.y) : "l"(v));
    return f;
}

// ---------------- cp.async helpers ----------------
__device__ __forceinline__ void cp16(unsigned dst, const void* src) {
    asm volatile("cp.async.cg.shared.global [%0], [%1], 16;" :: "r"(dst), "l"(src));
}
#define CP_COMMIT() asm volatile("cp.async.commit_group;")
#define CP_WAIT0()  asm volatile("cp.async.wait_group 0;")

// ---------------- scratch (device globals; no runtime alloc) ----------------
__device__ float g_pooled[(size_t)MB*CIN*PP];   // flat layout for FC1 (~205 MB)
__device__ float g_pad[(size_t)MB*CIN*256];     // padded 16x16 layout for conv (~256 MB)
__device__ float g_h[MB*HID];
__device__ float g_hpart[KS*MB*HID];
__device__ float g_csum[MB*OC];
__device__ float g_wT[CIN*9*OC];                // conv weights [cin*9][oc]
__device__ int   g_lvl[MB];
__device__ float g_boxp[MB*4];

// ---------------- setup: FPN level + scaled box params ----------------
__global__ void setup_boxes(const float* __restrict__ boxes,
                            const int* __restrict__ ih, const int* __restrict__ iw) {
    int m = blockIdx.x * blockDim.x + threadIdx.x;
    if (m >= MB) return;
    float x1 = boxes[m*4+0], y1 = boxes[m*4+1];
    float x2 = boxes[m*4+2], y2 = boxes[m*4+3];
    float alpha = (224.0f/800.0f) * fminf((float)(*ih), (float)(*iw));
    float bw = fabsf(x2-x1), bh = fabsf(y2-y1);
    float s = sqrtf(fmaxf(bw*bh, 1e-6f));
    float k = floorf(4.0f + log2f(s/alpha));
    float kl = fminf(fmaxf(k - 2.0f, 0.0f), 3.0f);
    int lvl = (int)kl;
    g_lvl[m] = lvl;
    float scale = 1.0f / (float)(4 << lvl);
    float x1s = x1*scale, y1s = y1*scale, x2s = x2*scale, y2s = y2*scale;
    g_boxp[m*4+0] = x1s;
    g_boxp[m*4+1] = y1s;
    g_boxp[m*4+2] = x2s - x1s;
    g_boxp[m*4+3] = y2s - y1s;
}

// ---------------- conv weight transpose: [oc][cin*9] -> [cin*9][oc] ----------------
__global__ void wconv_transpose(const float* __restrict__ w) {
    int i = blockIdx.x * 256 + threadIdx.x;
    if (i >= OC*CIN*9) return;
    int oc = i / (CIN*9);
    int r  = i % (CIN*9);
    g_wT[r*OC + oc] = w[i];
}

// ---------------- RoIAlign: block=(box m, channel c) ----------------
// t<196: one bin; writes flat (FC1) + padded (conv) layouts.
// t>=196: zero the 60 halo cells of the padded 16x16 tile.
__global__ void roi_kernel(const float* __restrict__ p2, const float* __restrict__ p3,
                           const float* __restrict__ p4, const float* __restrict__ p5,
                           const int* __restrict__ bidx) {
    int m = blockIdx.x;
    int c = blockIdx.y;
    int t = threadIdx.x;
    float* padBase = g_pad + ((size_t)m*CIN + c)*256;
    if (t >= PP) {
        int j = t - PP;            // 0..27  -> zero halo cells j, j+28, (j+56 if j<4)
        #pragma unroll
        for (int k = 0; k < 3; k++) {
            int idx = j + 28*k;
            if (idx < 60) {
                int cell;
                if      (idx < 16) cell = idx;                      // top row
                else if (idx < 32) cell = 240 + (idx - 16);          // bottom row
                else if (idx < 46) cell = (idx - 31) * 16;           // left col rows 1..14
                else               cell = (idx - 45) * 16 + 15;      // right col rows 1..14
                padBase[cell] = 0.0f;
            }
        }
        return;
    }
    int lvl = g_lvl[m];
    const float* f; int H, W;
    if      (lvl == 0) { f = p2; H = 200; W = 200; }
    else if (lvl == 1) { f = p3; H = 100; W = 100; }
    else if (lvl == 2) { f = p4; H = 50;  W = 50;  }
    else               { f = p5; H = 25;  W = 25;  }
    int b = bidx[m];
    float x1 = g_boxp[m*4+0], y1 = g_boxp[m*4+1];
    float dx = g_boxp[m*4+2], dy = g_boxp[m*4+3];
    int py = t / POOLSZ, px = t % POOLSZ;
    float gx = x1 + ((float)px + 0.5f) * (1.0f/POOLSZ) * dx;
    float gy = y1 + ((float)py + 0.5f) * (1.0f/POOLSZ) * dy;
    float x0f = floorf(gx), y0f = floorf(gy);
    float lx = gx - x0f, ly = gy - y0f;
    int xi0 = min(max((int)x0f,     0), W-1);
    int xi1 = min(max((int)x0f + 1, 0), W-1);
    int yi0 = min(max((int)y0f,     0), H-1);
    int yi1 = min(max((int)y0f + 1, 0), H-1);
    const float* base = f + ((size_t)(b*CIN + c)) * H * W;
    float v00 = base[yi0*W + xi0];
    float v01 = base[yi0*W + xi1];
    float v10 = base[yi1*W + xi0];
    float v11 = base[yi1*W + xi1];
    float val = v00*(1.f-ly)*(1.f-lx) + v01*(1.f-ly)*lx
              + v10*ly*(1.f-lx)       + v11*ly*lx;
    g_pooled[((size_t)m*CIN + c)*PP + t] = val;
    padBase[(py + 1)*16 + (px + 1)] = val;
}

// ---------------- FC1 GEMM (split-K, double-buffered, dist-2 prefetch) -------------
// [512 x 100352] @ [100352 x 1024] -> partials (no bias). 64x64 tile, 256 thr, f32x2.
#define BM 64
#define BN 64
#define BK 16
#define NKH ((KFC/KS)/BK)    // 3136
__global__ __launch_bounds__(256)
void gemm1_kernel(const float* __restrict__ B) {
    __shared__ __align__(16) float As[2][BK][BM+4];    // [buf][k][m]
    __shared__ __align__(16) float Bsd[2][BK][2*BN];   // [buf][k][2n], duplicated
    int t  = threadIdx.x;
    int mBase = blockIdx.y * BM;
    int nBase = blockIdx.x * BN;
    int ks    = blockIdx.z;
    int kBeg  = ks * (KFC/KS);
    int ty = t / 16, tx = t % 16;
    int arow = t / 4,  acol = (t % 4) * 4;    // A tile 64x16
    int brow = t / 16, bcol = (t % 16) * 4;   // B tile 16x64
    const float* Ap = g_pooled + (size_t)(mBase + arow) * KFC + kBeg + acol;
    const float* Bp = B + (size_t)(kBeg + brow) * HID + nBase + bcol;
    unsigned long long acc2[2][4];
    #pragma unroll
    for (int ip = 0; ip < 2; ip++)
        #pragma unroll
        for (int j = 0; j < 4; j++) acc2[ip][j] = 0ull;

    // prologue: stage 0 -> smem buf0; stage 1 -> regs
    float4 a1 = *(const float4*)(Ap);
    float4 b1 = *(const float4*)(Bp);
    As[0][acol+0][arow] = a1.x; As[0][acol+1][arow] = a1.y;
    As[0][acol+2][arow] = a1.z; As[0][acol+3][arow] = a1.w;
    {
        unsigned long long* bd = (unsigned long long*)&Bsd[0][brow][2*bcol];
        bd[0] = pk2(b1.x, b1.x); bd[1] = pk2(b1.y, b1.y);
        bd[2] = pk2(b1.z, b1.z); bd[3] = pk2(b1.w, b1.w);
    }
    __syncthreads();
    a1 = *(const float4*)(Ap + BK);
    b1 = *(const float4*)(Bp + (size_t)BK * HID);
    float4 a2, b2;
    int buf = 0;
    for (int k0 = 0; k0 < NKH; k0++) {
        if (k0 + 2 < NKH) {
            a2 = *(const float4*)(Ap + (k0+2)*BK);
            b2 = *(const float4*)(Bp + (size_t)(k0+2)*BK * HID);
        }
        #pragma unroll
        for (int kk = 0; kk < BK; kk++) {
            ulonglong2 ap  = *(const ulonglong2*)&As[buf][kk][ty*4];
            ulonglong2 b01 = *(const ulonglong2*)&Bsd[buf][kk][8*tx];
            ulonglong2 b23 = *(const ulonglong2*)&Bsd[buf][kk][8*tx+4];
            fma2(acc2[0][0], ap.x, b01.x);
            fma2(acc2[0][1], ap.x, b01.y);
            fma2(acc2[0][2], ap.x, b23.x);
            fma2(acc2[0][3], ap.x, b23.y);
            fma2(acc2[1][0], ap.y, b01.x);
            fma2(acc2[1][1], ap.y, b01.y);
            fma2(acc2[1][2], ap.y, b23.x);
            fma2(acc2[1][3], ap.y, b23.y);
        }
        if (k0 + 1 < NKH) {
            int nb = buf ^ 1;
            As[nb][acol+0][arow] = a1.x; As[nb][acol+1][arow] = a1.y;
            As[nb][acol+2][arow] = a1.z; As[nb][acol+3][arow] = a1.w;
            unsigned long long* bd = (unsigned long long*)&Bsd[nb][brow][2*bcol];
            bd[0] = pk2(b1.x, b1.x); bd[1] = pk2(b1.y, b1.y);
            bd[2] = pk2(b1.z, b1.z); bd[3] = pk2(b1.w, b1.w);
            __syncthreads();
            buf = nb;
            a1 = a2; b1 = b2;
        }
    }
    float* outp = g_hpart + (size_t)ks * MB * HID;
    #pragma unroll
    for (int ip = 0; ip < 2; ip++) {
        #pragma unroll
        for (int j = 0; j < 4; j++) {
            float2 v = upk(acc2[ip][j]);
            int n = nBase + tx*4 + j;
            int m0 = mBase + ty*4 + 2*ip;
            outp[(m0+0)*HID + n] = v.x;
            outp[(m0+1)*HID + n] = v.y;
        }
    }
}

// ---------------- FC1 combine: partials + bias, ReLU ----------------
__global__ void gemm1_combine(const float* __restrict__ bias) {
    int m = blockIdx.x;
    int n = threadIdx.x;              // HID = 1024 = blockDim
    int i = m*HID + n;
    float v = g_hpart[i] + g_hpart[MB*HID + i] + bias[n];
    g_h[i] = fmaxf(v, 0.0f);
}

// ---------------- conv 3x3 SAME (512->256) + bias + ReLU + spatial sum -------------
// block = (box m, oc-block of 64). 224 thr: pg = t>>3 (28 pixel groups of 7), ocg=t&7.
// cin chunked by 4, 2-stage cp.async pipeline from padded input.
#define CCH 4
#define NCH (CIN/CCH)      // 128
__global__ __launch_bounds__(224)
void conv_kernel(const float* __restrict__ bconv) {
    __shared__ __align__(16) float sIn[2][CCH*256];    // padded 16x16 per cin
    __shared__ __align__(16) float sW[2][CCH*9*64];    // [cin][k][oc64]
    __shared__ float sRed[28*64];
    int m = blockIdx.x;
    int ocBase = blockIdx.y * 64;
    int t = threadIdx.x;
    int pg  = t >> 3;
    int ocg = t & 7;
    int py  = pg >> 1;
    int x0  = (pg & 1) * 7;
    unsigned sInA[2], sWA[2];
    sInA[0] = (unsigned)__cvta_generic_to_shared(&sIn[0][0]);
    sInA[1] = (unsigned)__cvta_generic_to_shared(&sIn[1][0]);
    sWA[0]  = (unsigned)__cvta_generic_to_shared(&sW[0][0]);
    sWA[1]  = (unsigned)__cvta_generic_to_shared(&sW[1][0]);
    const float* inBase0 = g_pad + (size_t)m*CIN*256;
    const float* wBase0  = g_wT + ocBase;

    unsigned long long acc2[4][7];
    #pragma unroll
    for (int jp = 0; jp < 4; jp++)
        #pragma unroll
        for (int i = 0; i < 7; i++) acc2[jp][i] = 0ull;

    // issue stage cb into buffer bf: 256 input units + 576 weight units (16B each)
    auto issue = [&](int cb, int bf) {
        const float* inB = inBase0 + (size_t)cb*CCH*256;
        const float* wB  = wBase0 + (size_t)cb*(CCH*9)*OC;
        for (int u = t; u < 832; u += 224) {
            if (u < 256) {
                cp16(sInA[bf] + u*16, inB + u*4);
            } else {
                int v2  = u - 256;        // 0..575
                int row = v2 >> 4;        // 0..35  (cin*9+k)
                int c4  = v2 & 15;
                cp16(sWA[bf] + (row*64 + c4*4)*4, wB + row*OC + c4*4);
            }
        }
        CP_COMMIT();
    };

    issue(0, 0);
    for (int cb = 0; cb < NCH; cb++) {
        CP_WAIT0();
        __syncthreads();
        if (cb + 1 < NCH) issue(cb + 1, (cb + 1) & 1);
        int bf = cb & 1;
        #pragma unroll
        for (int cin = 0; cin < CCH; cin++) {
            #pragma unroll
            for (int ky = 0; ky < 3; ky++) {
                unsigned long long row[9];
                #pragma unroll
                for (int c = 0; c < 9; c++) {
                    float v = sIn[bf][cin*256 + (py + ky)*16 + (x0 + c)];
                    row[c] = pk2(v, v);
                }
                #pragma unroll
                for (int kx = 0; kx < 3; kx++) {
                    const ulonglong2* wp =
                        (const ulonglong2*)&sW[bf][(cin*9 + ky*3 + kx)*64 + ocg*8];
                    ulonglong2 wa = wp[0];
                    ulonglong2 wb = wp[1];
                    #pragma unroll
                    for (int i = 0; i < 7; i++) {
                        fma2(acc2[0][i], wa.x, row[i + kx]);
                        fma2(acc2[1][i], wa.y, row[i + kx]);
                        fma2(acc2[2][i], wb.x, row[i + kx]);
                        fma2(acc2[3][i], wb.y, row[i + kx]);
                    }
                }
            }
        }
        __syncthreads();
    }
    // bias + relu + per-thread partial spatial sum, then smem reduce over pg
    #pragma unroll
    for (int jp = 0; jp < 4; jp++) {
        float bv0 = bconv[ocBase + ocg*8 + 2*jp + 0];
        float bv1 = bconv[ocBase + ocg*8 + 2*jp + 1];
        float s0 = 0.0f, s1 = 0.0f;
        #pragma unroll
        for (int i = 0; i < 7; i++) {
            float2 v = upk(acc2[jp][i]);
            s0 += fmaxf(v.x + bv0, 0.0f);
            s1 += fmaxf(v.y + bv1, 0.0f);
        }
        sRed[pg*64 + ocg*8 + 2*jp + 0] = s0;
        sRed[pg*64 + ocg*8 + 2*jp + 1] = s1;
    }
    __syncthreads();
    if (t < 64) {
        float tot = 0.0f;
        #pragma unroll
        for (int pgi = 0; pgi < 28; pgi++) tot += sRed[pgi*64 + t];
        g_csum[m*OC + ocBase + t] = tot;
    }
}

// ---------------- cls / box heads + softmax ----------------
__global__ void cls_kernel(const float* __restrict__ wcls, const float* __restrict__ bcls,
                           const float* __restrict__ wbox, const float* __restrict__ bbox,
                           float* __restrict__ out) {
    int m = blockIdx.x;
    int t = threadIdx.x;
    __shared__ float sh[HID];
    __shared__ float lg[NCLS];
    __shared__ float red[2];
    for (int i = t; i < HID; i += 128) sh[i] = g_h[m*HID + i];
    __syncthreads();
    if (t < NCLS) {
        float a = bcls[t], r = bbox[t];
        #pragma unroll 8
        for (int k = 0; k < HID; k++) {
            float hv = sh[k];
            a += hv * wcls[k*NCLS + t];
            r += hv * wbox[k*NCLS + t];
        }
        lg[t] = a;
        out[O1 + m*NCLS + t] = r;
    }
    __syncthreads();
    if (t == 0) {
        float mx = lg[0];
        for (int i = 1; i < NCLS; i++) mx = fmaxf(mx, lg[i]);
        red[0] = mx;
    }
    __syncthreads();
    if (t < NCLS) lg[t] = expf(lg[t] - red[0]);
    __syncthreads();
    if (t == 0) {
        float s = 0.0f;
        for (int i = 0; i < NCLS; i++) s += lg[i];
        red[1] = s;
    }
    __syncthreads();
    if (t < NCLS) out[m*NCLS + t] = lg[t] / red[1];
}

// ---------------- mask head: mean -> FC -> sigmoid ----------------
__global__ void mask_kernel(const float* __restrict__ wmfc, const float* __restrict__ bmfc,
                            float* __restrict__ out) {
    int m = blockIdx.x;
    int t = threadIdx.x;
    __shared__ float sm_[OC];
    for (int i = t; i < OC; i += 96) sm_[i] = g_csum[m*OC + i] * (1.0f/196.0f);
    __syncthreads();
    if (t < NCLS) {
        float a = bmfc[t];
        for (int o = 0; o < OC; o++) a += sm_[o] * wmfc[o*NCLS + t];
        out[2*O1 + m*NCLS + t] = 1.0f / (1.0f + expf(-a));
    }
}

// ---------------- launch ----------------
extern "C" void kernel_launch(void* const* d_in, const int* in_sizes, int n_in,
                              void* d_out, int out_size) {
    const float* p2    = (const float*)d_in[0];
    const float* p3    = (const float*)d_in[1];
    const float* p4    = (const float*)d_in[2];
    const float* p5    = (const float*)d_in[3];
    const float* boxes = (const float*)d_in[4];
    const int*   bidx  = (const int*)  d_in[5];
    const float* wfc1  = (const float*)d_in[6];
    const float* bfc1  = (const float*)d_in[7];
    const float* wcls  = (const float*)d_in[8];
    const float* bcls  = (const float*)d_in[9];
    const float* wbox  = (const float*)d_in[10];
    const float* bbox  = (const float*)d_in[11];
    const float* wconv = (const float*)d_in[12];
    const float* bconv = (const float*)d_in[13];
    const float* wmfc  = (const float*)d_in[14];
    const float* bmfc  = (const float*)d_in[15];
    const int*   ih    = (const int*)  d_in[16];
    const int*   iw    = (const int*)  d_in[17];
    float* out = (float*)d_out;

    setup_boxes<<<1, 512>>>(boxes, ih, iw);
    wconv_transpose<<<(OC*CIN*9 + 255)/256, 256>>>(wconv);
    roi_kernel<<<dim3(MB, CIN), 224>>>(p2, p3, p4, p5, bidx);
    gemm1_kernel<<<dim3(HID/BN, MB/BM, KS), 256>>>(wfc1);
    gemm1_combine<<<MB, HID>>>(bfc1);
    conv_kernel<<<dim3(MB, OC/64), 224>>>(bconv);
    cls_kernel<<<MB, 128>>>(wcls, bcls, wbox, bbox, out);
    mask_kernel<<<MB, 96>>>(wmfc, bmfc, out);
}

// round 17
// speedup vs baseline: 2.2887x; 1.7314x over previous
#include <cuda_runtime.h>
#include <math.h>

// ---------------- problem constants (shape-specialized) ----------------
#define NB      2            // batch
#define MB      512          // boxes
#define CIN     512          // feature channels
#define POOLSZ  14
#define PP      196          // 14*14
#define HID     1024
#define NCLS    81
#define KFC     (CIN*PP)     // 100352
#define OC      256          // conv out channels
#define O1      (MB*NCLS)    // 41472 per-output stride in d_out
#define KS      4            // split-K factor for FC1

// ---------------- packed fp32x2 helpers (sm_103a FFMA2 path) ----------------
__device__ __forceinline__ unsigned long long pk2(float x, float y) {
    unsigned long long r;
    asm("mov.b64 %0, {%1, %2};" : "=l"(r) : "f"(x), "f"(y));
    return r;
}
__device__ __forceinline__ void fma2(unsigned long long& d, unsigned long long a,
                                     unsigned long long b) {
    asm("fma.rn.f32x2 %0, %1, %2, %3;" : "=l"(d) : "l"(a), "l"(b), "l"(d));
}
__device__ __forceinline__ float2 upk(unsigned long long v) {
    float2 f;
    asm("mov.b64 {%0, %1}, %2;" : "=f"(f.x), "=f"(f.y) : "l"(v));
    return f;
}

// ---------------- cp.async helpers ----------------
__device__ __forceinline__ void cp16(unsigned dst, const void* src) {
    asm volatile("cp.async.cg.shared.global [%0], [%1], 16;" :: "r"(dst), "l"(src));
}
#define CP_COMMIT() asm volatile("cp.async.commit_group;")
#define CP_WAIT0()  asm volatile("cp.async.wait_group 0;")

// ---------------- scratch (device globals; no runtime alloc) ----------------
__device__ float g_pooled[(size_t)MB*CIN*PP];   // flat layout for FC1 (~205 MB)
__device__ float g_pad[(size_t)MB*CIN*256];     // padded 16x16 layout for conv (~256 MB)
__device__ float g_h[MB*HID];
__device__ float g_hpart[KS*MB*HID];
__device__ float g_csum[MB*OC];
__device__ float g_wT[CIN*9*OC];                // conv weights [cin*9][oc]
__device__ int   g_lvl[MB];
__device__ float g_boxp[MB*4];

// ---------------- setup: FPN level + scaled box params ----------------
__global__ void setup_boxes(const float* __restrict__ boxes,
                            const int* __restrict__ ih, const int* __restrict__ iw) {
    int m = blockIdx.x * blockDim.x + threadIdx.x;
    if (m >= MB) return;
    float x1 = boxes[m*4+0], y1 = boxes[m*4+1];
    float x2 = boxes[m*4+2], y2 = boxes[m*4+3];
    float alpha = (224.0f/800.0f) * fminf((float)(*ih), (float)(*iw));
    float bw = fabsf(x2-x1), bh = fabsf(y2-y1);
    float s = sqrtf(fmaxf(bw*bh, 1e-6f));
    float k = floorf(4.0f + log2f(s/alpha));
    float kl = fminf(fmaxf(k - 2.0f, 0.0f), 3.0f);
    int lvl = (int)kl;
    g_lvl[m] = lvl;
    float scale = 1.0f / (float)(4 << lvl);
    float x1s = x1*scale, y1s = y1*scale, x2s = x2*scale, y2s = y2*scale;
    g_boxp[m*4+0] = x1s;
    g_boxp[m*4+1] = y1s;
    g_boxp[m*4+2] = x2s - x1s;
    g_boxp[m*4+3] = y2s - y1s;
}

// ---------------- conv weight transpose: [oc][cin*9] -> [cin*9][oc] ----------------
__global__ void wconv_transpose(const float* __restrict__ w) {
    int i = blockIdx.x * 256 + threadIdx.x;
    if (i >= OC*CIN*9) return;
    int oc = i / (CIN*9);
    int r  = i % (CIN*9);
    g_wT[r*OC + oc] = w[i];
}

// ---------------- RoIAlign: block=(box m, channel c) ----------------
__global__ void roi_kernel(const float* __restrict__ p2, const float* __restrict__ p3,
                           const float* __restrict__ p4, const float* __restrict__ p5,
                           const int* __restrict__ bidx) {
    int m = blockIdx.x;
    int c = blockIdx.y;
    int t = threadIdx.x;
    float* padBase = g_pad + ((size_t)m*CIN + c)*256;
    if (t >= PP) {
        int j = t - PP;            // 0..27  -> zero halo cells
        #pragma unroll
        for (int k = 0; k < 3; k++) {
            int idx = j + 28*k;
            if (idx < 60) {
                int cell;
                if      (idx < 16) cell = idx;                      // top row
                else if (idx < 32) cell = 240 + (idx - 16);          // bottom row
                else if (idx < 46) cell = (idx - 31) * 16;           // left col rows 1..14
                else               cell = (idx - 45) * 16 + 15;      // right col rows 1..14
                padBase[cell] = 0.0f;
            }
        }
        return;
    }
    int lvl = g_lvl[m];
    const float* f; int H, W;
    if      (lvl == 0) { f = p2; H = 200; W = 200; }
    else if (lvl == 1) { f = p3; H = 100; W = 100; }
    else if (lvl == 2) { f = p4; H = 50;  W = 50;  }
    else               { f = p5; H = 25;  W = 25;  }
    int b = bidx[m];
    float x1 = g_boxp[m*4+0], y1 = g_boxp[m*4+1];
    float dx = g_boxp[m*4+2], dy = g_boxp[m*4+3];
    int py = t / POOLSZ, px = t % POOLSZ;
    float gx = x1 + ((float)px + 0.5f) * (1.0f/POOLSZ) * dx;
    float gy = y1 + ((float)py + 0.5f) * (1.0f/POOLSZ) * dy;
    float x0f = floorf(gx), y0f = floorf(gy);
    float lx = gx - x0f, ly = gy - y0f;
    int xi0 = min(max((int)x0f,     0), W-1);
    int xi1 = min(max((int)x0f + 1, 0), W-1);
    int yi0 = min(max((int)y0f,     0), H-1);
    int yi1 = min(max((int)y0f + 1, 0), H-1);
    const float* base = f + ((size_t)(b*CIN + c)) * H * W;
    float v00 = base[yi0*W + xi0];
    float v01 = base[yi0*W + xi1];
    float v10 = base[yi1*W + xi0];
    float v11 = base[yi1*W + xi1];
    float val = v00*(1.f-ly)*(1.f-lx) + v01*(1.f-ly)*lx
              + v10*ly*(1.f-lx)       + v11*ly*lx;
    g_pooled[((size_t)m*CIN + c)*PP + t] = val;
    padBase[(py + 1)*16 + (px + 1)] = val;
}

// ---------------- FC1 GEMM v3: warp-dedup tiling + cp.async double buffer --------
// Block 128m x 64n, 128 threads (4 warps), per-thread 8m x 8n, split-K=4.
// A smem [m][k] (k-chunks XOR-swizzled), B smem [k][n] natural. f32x2 FMAs:
// a broadcast-dup {a,a} (scalar LDS + pack), b natural pairs {n,n+1}.
#define BM 128
#define BN 64
#define BK 32
#define NKH ((KFC/KS)/BK)    // 784
__global__ __launch_bounds__(128)
void gemm1_kernel(const float* __restrict__ B) {
    __shared__ __align__(16) float As[2][BM*BK];    // [m][k], chunk-swizzled
    __shared__ __align__(16) float Bs[2][BK*BN];    // [k][n]
    int t    = threadIdx.x;
    int wid  = t >> 5;
    int lane = t & 31;
    int mg   = lane >> 3;          // 0..3
    int ng   = lane & 7;           // 0..7
    int mBase = blockIdx.y * BM;
    int nBase = blockIdx.x * BN;
    int ks    = blockIdx.z;
    int kBeg  = ks * (KFC/KS);

    unsigned asA[2], bsA[2];
    asA[0] = (unsigned)__cvta_generic_to_shared(&As[0][0]);
    asA[1] = (unsigned)__cvta_generic_to_shared(&As[1][0]);
    bsA[0] = (unsigned)__cvta_generic_to_shared(&Bs[0][0]);
    bsA[1] = (unsigned)__cvta_generic_to_shared(&Bs[1][0]);

    unsigned long long acc2[8][4];   // [m j][n-pair]
    #pragma unroll
    for (int j = 0; j < 8; j++)
        #pragma unroll
        for (int p = 0; p < 4; p++) acc2[j][p] = 0ull;

    // cp.async stage: A = 128 rows x 8 chunks(16B) = 1024 chunks -> 8/thread
    //                 B = 32 rows x 16 chunks      = 512 chunks  -> 4/thread
    auto issue = [&](int k0, int bf) {
        long kb = (long)kBeg + (long)k0 * BK;
        #pragma unroll
        for (int i = 0; i < 8; i++) {
            int idx  = t + i * 128;
            int arow = idx >> 3;
            int c4   = idx & 7;
            int c4s  = c4 ^ ((arow >> 3) & 3);
            cp16(asA[bf] + (unsigned)(arow*BK + c4s*4)*4,
                 g_pooled + (size_t)(mBase + arow) * KFC + kb + c4*4);
        }
        #pragma unroll
        for (int i = 0; i < 4; i++) {
            int idx  = t + i * 128;
            int brow = idx >> 4;
            int c16  = idx & 15;
            cp16(bsA[bf] + (unsigned)(brow*BN + c16*4)*4,
                 B + (size_t)(kb + brow) * HID + nBase + c16*4);
        }
        CP_COMMIT();
    };

    int aRowBase = (wid*32 + mg*8) * BK;   // float index of this lane's first m-row
    issue(0, 0);
    for (int k0 = 0; k0 < NKH; k0++) {
        CP_WAIT0();
        __syncthreads();
        if (k0 + 1 < NKH) issue(k0 + 1, (k0 + 1) & 1);
        int bf = k0 & 1;
        const float* as = &As[bf][0];
        const float* bs = &Bs[bf][0];
        #pragma unroll
        for (int kk = 0; kk < BK; kk++) {
            int kc   = kk >> 2;
            int kr   = kk & 3;
            int aoff = aRowBase + (kc ^ mg)*4 + kr;
            // b pairs: Bs[kk][ng*8 .. +7] as 4 x 8B
            ulonglong2 b01 = *(const ulonglong2*)&bs[kk*BN + ng*8];
            ulonglong2 b23 = *(const ulonglong2*)&bs[kk*BN + ng*8 + 4];
            #pragma unroll
            for (int j = 0; j < 8; j++) {
                float av = as[aoff + j*BK];
                unsigned long long ad = pk2(av, av);
                fma2(acc2[j][0], ad, b01.x);
                fma2(acc2[j][1], ad, b01.y);
                fma2(acc2[j][2], ad, b23.x);
                fma2(acc2[j][3], ad, b23.y);
            }
        }
        __syncthreads();
    }
    float* outp = g_hpart + (size_t)ks * MB * HID;
    #pragma unroll
    for (int j = 0; j < 8; j++) {
        int m = mBase + wid*32 + mg*8 + j;
        #pragma unroll
        for (int p = 0; p < 4; p++) {
            float2 v = upk(acc2[j][p]);
            int n = nBase + ng*8 + 2*p;
            *(float2*)&outp[(size_t)m*HID + n] = v;
        }
    }
}

// ---------------- FC1 combine: partials + bias, ReLU ----------------
__global__ void gemm1_combine(const float* __restrict__ bias) {
    int m = blockIdx.x;
    int n = threadIdx.x;              // HID = 1024 = blockDim
    int i = m*HID + n;
    float v = bias[n];
    #pragma unroll
    for (int s = 0; s < KS; s++) v += g_hpart[(size_t)s*MB*HID + i];
    g_h[i] = fmaxf(v, 0.0f);
}

// ---------------- conv 3x3 SAME (512->256) + bias + ReLU + spatial sum -------------
#define CCH 4
#define NCH (CIN/CCH)      // 128
__global__ __launch_bounds__(224)
void conv_kernel(const float* __restrict__ bconv) {
    __shared__ __align__(16) float sIn[2][CCH*256];    // padded 16x16 per cin
    __shared__ __align__(16) float sW[2][CCH*9*64];    // [cin][k][oc64]
    __shared__ float sRed[28*64];
    int m = blockIdx.x;
    int ocBase = blockIdx.y * 64;
    int t = threadIdx.x;
    int pg  = t >> 3;
    int ocg = t & 7;
    int py  = pg >> 1;
    int x0  = (pg & 1) * 7;
    unsigned sInA[2], sWA[2];
    sInA[0] = (unsigned)__cvta_generic_to_shared(&sIn[0][0]);
    sInA[1] = (unsigned)__cvta_generic_to_shared(&sIn[1][0]);
    sWA[0]  = (unsigned)__cvta_generic_to_shared(&sW[0][0]);
    sWA[1]  = (unsigned)__cvta_generic_to_shared(&sW[1][0]);
    const float* inBase0 = g_pad + (size_t)m*CIN*256;
    const float* wBase0  = g_wT + ocBase;

    unsigned long long acc2[4][7];
    #pragma unroll
    for (int jp = 0; jp < 4; jp++)
        #pragma unroll
        for (int i = 0; i < 7; i++) acc2[jp][i] = 0ull;

    auto issue = [&](int cb, int bf) {
        const float* inB = inBase0 + (size_t)cb*CCH*256;
        const float* wB  = wBase0 + (size_t)cb*(CCH*9)*OC;
        for (int u = t; u < 832; u += 224) {
            if (u < 256) {
                cp16(sInA[bf] + u*16, inB + u*4);
            } else {
                int v2  = u - 256;        // 0..575
                int row = v2 >> 4;        // 0..35  (cin*9+k)
                int c4  = v2 & 15;
                cp16(sWA[bf] + (row*64 + c4*4)*4, wB + row*OC + c4*4);
            }
        }
        CP_COMMIT();
    };

    issue(0, 0);
    for (int cb = 0; cb < NCH; cb++) {
        CP_WAIT0();
        __syncthreads();
        if (cb + 1 < NCH) issue(cb + 1, (cb + 1) & 1);
        int bf = cb & 1;
        #pragma unroll
        for (int cin = 0; cin < CCH; cin++) {
            #pragma unroll
            for (int ky = 0; ky < 3; ky++) {
                unsigned long long row[9];
                #pragma unroll
                for (int c = 0; c < 9; c++) {
                    float v = sIn[bf][cin*256 + (py + ky)*16 + (x0 + c)];
                    row[c] = pk2(v, v);
                }
                #pragma unroll
                for (int kx = 0; kx < 3; kx++) {
                    const ulonglong2* wp =
                        (const ulonglong2*)&sW[bf][(cin*9 + ky*3 + kx)*64 + ocg*8];
                    ulonglong2 wa = wp[0];
                    ulonglong2 wb = wp[1];
                    #pragma unroll
                    for (int i = 0; i < 7; i++) {
                        fma2(acc2[0][i], wa.x, row[i + kx]);
                        fma2(acc2[1][i], wa.y, row[i + kx]);
                        fma2(acc2[2][i], wb.x, row[i + kx]);
                        fma2(acc2[3][i], wb.y, row[i + kx]);
                    }
                }
            }
        }
        __syncthreads();
    }
    #pragma unroll
    for (int jp = 0; jp < 4; jp++) {
        float bv0 = bconv[ocBase + ocg*8 + 2*jp + 0];
        float bv1 = bconv[ocBase + ocg*8 + 2*jp + 1];
        float s0 = 0.0f, s1 = 0.0f;
        #pragma unroll
        for (int i = 0; i < 7; i++) {
            float2 v = upk(acc2[jp][i]);
            s0 += fmaxf(v.x + bv0, 0.0f);
            s1 += fmaxf(v.y + bv1, 0.0f);
        }
        sRed[pg*64 + ocg*8 + 2*jp + 0] = s0;
        sRed[pg*64 + ocg*8 + 2*jp + 1] = s1;
    }
    __syncthreads();
    if (t < 64) {
        float tot = 0.0f;
        #pragma unroll
        for (int pgi = 0; pgi < 28; pgi++) tot += sRed[pgi*64 + t];
        g_csum[m*OC + ocBase + t] = tot;
    }
}

// ---------------- cls / box heads + softmax ----------------
__global__ void cls_kernel(const float* __restrict__ wcls, const float* __restrict__ bcls,
                           const float* __restrict__ wbox, const float* __restrict__ bbox,
                           float* __restrict__ out) {
    int m = blockIdx.x;
    int t = threadIdx.x;
    __shared__ float sh[HID];
    __shared__ float lg[NCLS];
    __shared__ float red[2];
    for (int i = t; i < HID; i += 128) sh[i] = g_h[m*HID + i];
    __syncthreads();
    if (t < NCLS) {
        float a = bcls[t], r = bbox[t];
        #pragma unroll 8
        for (int k = 0; k < HID; k++) {
            float hv = sh[k];
            a += hv * wcls[k*NCLS + t];
            r += hv * wbox[k*NCLS + t];
        }
        lg[t] = a;
        out[O1 + m*NCLS + t] = r;
    }
    __syncthreads();
    if (t == 0) {
        float mx = lg[0];
        for (int i = 1; i < NCLS; i++) mx = fmaxf(mx, lg[i]);
        red[0] = mx;
    }
    __syncthreads();
    if (t < NCLS) lg[t] = expf(lg[t] - red[0]);
    __syncthreads();
    if (t == 0) {
        float s = 0.0f;
        for (int i = 0; i < NCLS; i++) s += lg[i];
        red[1] = s;
    }
    __syncthreads();
    if (t < NCLS) out[m*NCLS + t] = lg[t] / red[1];
}

// ---------------- mask head: mean -> FC -> sigmoid ----------------
__global__ void mask_kernel(const float* __restrict__ wmfc, const float* __restrict__ bmfc,
                            float* __restrict__ out) {
    int m = blockIdx.x;
    int t = threadIdx.x;
    __shared__ float sm_[OC];
    for (int i = t; i < OC; i += 96) sm_[i] = g_csum[m*OC + i] * (1.0f/196.0f);
    __syncthreads();
    if (t < NCLS) {
        float a = bmfc[t];
        for (int o = 0; o < OC; o++) a += sm_[o] * wmfc[o*NCLS + t];
        out[2*O1 + m*NCLS + t] = 1.0f / (1.0f + expf(-a));
    }
}

// ---------------- launch ----------------
extern "C" void kernel_launch(void* const* d_in, const int* in_sizes, int n_in,
                              void* d_out, int out_size) {
    const float* p2    = (const float*)d_in[0];
    const float* p3    = (const float*)d_in[1];
    const float* p4    = (const float*)d_in[2];
    const float* p5    = (const float*)d_in[3];
    const float* boxes = (const float*)d_in[4];
    const int*   bidx  = (const int*)  d_in[5];
    const float* wfc1  = (const float*)d_in[6];
    const float* bfc1  = (const float*)d_in[7];
    const float* wcls  = (const float*)d_in[8];
    const float* bcls  = (const float*)d_in[9];
    const float* wbox  = (const float*)d_in[10];
    const float* bbox  = (const float*)d_in[11];
    const float* wconv = (const float*)d_in[12];
    const float* bconv = (const float*)d_in[13];
    const float* wmfc  = (const float*)d_in[14];
    const float* bmfc  = (const float*)d_in[15];
    const int*   ih    = (const int*)  d_in[16];
    const int*   iw    = (const int*)  d_in[17];
    float* out = (float*)d_out;

    setup_boxes<<<1, 512>>>(boxes, ih, iw);
    wconv_transpose<<<(OC*CIN*9 + 255)/256, 256>>>(wconv);
    roi_kernel<<<dim3(MB, CIN), 224>>>(p2, p3, p4, p5, bidx);
    gemm1_kernel<<<dim3(HID/BN, MB/BM, KS), 128>>>(wfc1);
    gemm1_combine<<<MB, HID>>>(bfc1);
    conv_kernel<<<dim3(MB, OC/64), 224>>>(bconv);
    cls_kernel<<<MB, 128>>>(wcls, bcls, wbox, bbox, out);
    mask_kernel<<<MB, 96>>>(wmfc, bmfc, out);
}